// round 4
// baseline (speedup 1.0000x reference)
#include <cuda_runtime.h>
#include <math.h>

#define NN 50000
#define EE 800000

// ---------------- scratch ----------------
__device__ float g_qkv[NN * 384];     // [node][ q | k | v ]
__device__ float g_agg[NN * 128];
__device__ int   g_cnt[NN];
__device__ int   g_off[NN + 1];
__device__ int   g_list[EE];

// ---------------- streams/events (created at static init, outside mem checkpoints) ----
static cudaStream_t s_side;
static cudaEvent_t  s_evFork, s_evJoin;
static struct StreamInit {
    StreamInit() {
        cudaStreamCreateWithFlags(&s_side, cudaStreamNonBlocking);
        cudaEventCreateWithFlags(&s_evFork, cudaEventDisableTiming);
        cudaEventCreateWithFlags(&s_evJoin, cudaEventDisableTiming);
    }
} s_streamInit;

// ---------------- CSR build ----------------
__global__ void zero_cnt_k() {
    int i = blockIdx.x * blockDim.x + threadIdx.x;
    if (i < NN) g_cnt[i] = 0;
}

__global__ void hist_k(const int* __restrict__ ei) {
    int e = blockIdx.x * blockDim.x + threadIdx.x;
    if (e < EE) atomicAdd(&g_cnt[ei[EE + e]], 1);
}

__global__ __launch_bounds__(1024) void scan_k() {
    __shared__ int ssum[1024];
    const int T = 1024;
    const int CH = (NN + T - 1) / T;
    int t = threadIdx.x;
    int base = t * CH;

    int loc = 0;
    for (int i = 0; i < CH; i++) {
        int idx = base + i;
        if (idx < NN) loc += g_cnt[idx];
    }
    ssum[t] = loc;
    __syncthreads();
    for (int o = 1; o < T; o <<= 1) {
        int v = (t >= o) ? ssum[t - o] : 0;
        __syncthreads();
        ssum[t] += v;
        __syncthreads();
    }
    int run = (t == 0) ? 0 : ssum[t - 1];
    for (int i = 0; i < CH; i++) {
        int idx = base + i;
        if (idx < NN) {
            int c = g_cnt[idx];
            g_off[idx] = run;
            g_cnt[idx] = 0;
            run += c;
        }
    }
    if (t == T - 1) g_off[NN] = run;
}

__global__ void scatter_k(const int* __restrict__ ei) {
    int e = blockIdx.x * blockDim.x + threadIdx.x;
    if (e < EE) {
        int dst = ei[EE + e];
        int pos = atomicAdd(&g_cnt[dst], 1);
        g_list[g_off[dst] + pos] = e;
    }
}

// ---------------- TF32 helpers ----------------
__device__ __forceinline__ unsigned f2tf32(float f) {
    unsigned u;
    asm("cvt.rna.tf32.f32 %0, %1;" : "=r"(u) : "f"(f));
    return u;
}

__device__ __forceinline__ void mma_tf32(
    float& c0, float& c1, float& c2, float& c3,
    unsigned a0, unsigned a1, unsigned a2, unsigned a3,
    unsigned b0, unsigned b1)
{
    asm volatile(
        "mma.sync.aligned.m16n8k8.row.col.f32.tf32.tf32.f32 "
        "{%0,%1,%2,%3}, {%4,%5,%6,%7}, {%8,%9}, {%0,%1,%2,%3};"
        : "+f"(c0), "+f"(c1), "+f"(c2), "+f"(c3)
        : "r"(a0), "r"(a1), "r"(a2), "r"(a3), "r"(b0), "r"(b1));
}

#define BK 16

// ---------------- TF32 GEMM [N,128]x[128,128]+bias (QKV variant, static smem) ----------
__global__ __launch_bounds__(256) void gemm_tf32(
    const float* __restrict__ A, const float* __restrict__ W,
    const float* __restrict__ bias, float* __restrict__ C,
    int ldc, int coloff)
{
    __shared__ unsigned As[2][BK][136];
    __shared__ unsigned Bs[2][BK][128];

    const int t    = threadIdx.x;
    const int wid  = t >> 5;
    const int lane = t & 31;
    const int wm   = wid & 1;
    const int wn   = wid >> 1;
    const int tig  = lane & 3;
    const int grp  = lane >> 2;
    const int rowBase = blockIdx.x * 128;

    float acc[4][4][4];
#pragma unroll
    for (int mi = 0; mi < 4; mi++)
#pragma unroll
        for (int ni = 0; ni < 4; ni++)
#pragma unroll
            for (int r = 0; r < 4; r++) acc[mi][ni][r] = 0.f;

    const int aRow0 = t >> 2;
    const int aC0   = (t & 3) << 2;
    const int aRow1 = (t + 256) >> 2;
    const int bK0 = t >> 5;
    const int bN0 = (t & 31) << 2;
    const int bK1 = bK0 + 8;

    const bool aOk0 = rowBase + aRow0 < NN;
    const bool aOk1 = rowBase + aRow1 < NN;
    const float* aP0 = A + (size_t)(rowBase + aRow0) * 128 + aC0;
    const float* aP1 = A + (size_t)(rowBase + aRow1) * 128 + aC0;

    float4 fa0 = make_float4(0.f,0.f,0.f,0.f), fa1 = fa0, fb0, fb1;
    if (aOk0) fa0 = *reinterpret_cast<const float4*>(aP0);
    if (aOk1) fa1 = *reinterpret_cast<const float4*>(aP1);
    fb0 = *reinterpret_cast<const float4*>(W + (size_t)bK0 * 128 + bN0);
    fb1 = *reinterpret_cast<const float4*>(W + (size_t)bK1 * 128 + bN0);

    int buf = 0;
    {
        As[0][aC0+0][aRow0] = f2tf32(fa0.x); As[0][aC0+1][aRow0] = f2tf32(fa0.y);
        As[0][aC0+2][aRow0] = f2tf32(fa0.z); As[0][aC0+3][aRow0] = f2tf32(fa0.w);
        As[0][aC0+0][aRow1] = f2tf32(fa1.x); As[0][aC0+1][aRow1] = f2tf32(fa1.y);
        As[0][aC0+2][aRow1] = f2tf32(fa1.z); As[0][aC0+3][aRow1] = f2tf32(fa1.w);
        Bs[0][bK0][bN0+0] = f2tf32(fb0.x); Bs[0][bK0][bN0+1] = f2tf32(fb0.y);
        Bs[0][bK0][bN0+2] = f2tf32(fb0.z); Bs[0][bK0][bN0+3] = f2tf32(fb0.w);
        Bs[0][bK1][bN0+0] = f2tf32(fb1.x); Bs[0][bK1][bN0+1] = f2tf32(fb1.y);
        Bs[0][bK1][bN0+2] = f2tf32(fb1.z); Bs[0][bK1][bN0+3] = f2tf32(fb1.w);
    }
    __syncthreads();

    for (int kb = 0; kb < 8; kb++) {
        const int nk = (kb + 1) * BK;
        if (kb < 7) {
            fa0 = make_float4(0.f,0.f,0.f,0.f); fa1 = fa0;
            if (aOk0) fa0 = *reinterpret_cast<const float4*>(aP0 + nk);
            if (aOk1) fa1 = *reinterpret_cast<const float4*>(aP1 + nk);
            fb0 = *reinterpret_cast<const float4*>(W + (size_t)(nk + bK0) * 128 + bN0);
            fb1 = *reinterpret_cast<const float4*>(W + (size_t)(nk + bK1) * 128 + bN0);
        }

#pragma unroll
        for (int ks = 0; ks < 2; ks++) {
            const int k0 = ks * 8;
            unsigned a[4][4];
#pragma unroll
            for (int mi = 0; mi < 4; mi++) {
                int mr = wm * 64 + mi * 16 + grp;
                a[mi][0] = As[buf][k0 + tig][mr];
                a[mi][1] = As[buf][k0 + tig][mr + 8];
                a[mi][2] = As[buf][k0 + tig + 4][mr];
                a[mi][3] = As[buf][k0 + tig + 4][mr + 8];
            }
            unsigned b[4][2];
#pragma unroll
            for (int ni = 0; ni < 4; ni++) {
                int nc = wn * 32 + ni * 8 + grp;
                b[ni][0] = Bs[buf][k0 + tig][nc];
                b[ni][1] = Bs[buf][k0 + tig + 4][nc];
            }
#pragma unroll
            for (int mi = 0; mi < 4; mi++)
#pragma unroll
                for (int ni = 0; ni < 4; ni++)
                    mma_tf32(acc[mi][ni][0], acc[mi][ni][1], acc[mi][ni][2], acc[mi][ni][3],
                             a[mi][0], a[mi][1], a[mi][2], a[mi][3],
                             b[ni][0], b[ni][1]);
        }

        if (kb < 7) {
            int nb = buf ^ 1;
            As[nb][aC0+0][aRow0] = f2tf32(fa0.x); As[nb][aC0+1][aRow0] = f2tf32(fa0.y);
            As[nb][aC0+2][aRow0] = f2tf32(fa0.z); As[nb][aC0+3][aRow0] = f2tf32(fa0.w);
            As[nb][aC0+0][aRow1] = f2tf32(fa1.x); As[nb][aC0+1][aRow1] = f2tf32(fa1.y);
            As[nb][aC0+2][aRow1] = f2tf32(fa1.z); As[nb][aC0+3][aRow1] = f2tf32(fa1.w);
            Bs[nb][bK0][bN0+0] = f2tf32(fb0.x); Bs[nb][bK0][bN0+1] = f2tf32(fb0.y);
            Bs[nb][bK0][bN0+2] = f2tf32(fb0.z); Bs[nb][bK0][bN0+3] = f2tf32(fb0.w);
            Bs[nb][bK1][bN0+0] = f2tf32(fb1.x); Bs[nb][bK1][bN0+1] = f2tf32(fb1.y);
            Bs[nb][bK1][bN0+2] = f2tf32(fb1.z); Bs[nb][bK1][bN0+3] = f2tf32(fb1.w);
            __syncthreads();
            buf = nb;
        }
    }

#pragma unroll
    for (int mi = 0; mi < 4; mi++) {
        int r0 = rowBase + wm * 64 + mi * 16 + grp;
        int r1 = r0 + 8;
#pragma unroll
        for (int ni = 0; ni < 4; ni++) {
            int c = wn * 32 + ni * 8 + tig * 2;
            float b0 = bias[c], b1 = bias[c + 1];
            if (r0 < NN) {
                float2 o = make_float2(acc[mi][ni][0] + b0, acc[mi][ni][1] + b1);
                *reinterpret_cast<float2*>(C + (size_t)r0 * ldc + coloff + c) = o;
            }
            if (r1 < NN) {
                float2 o = make_float2(acc[mi][ni][2] + b0, acc[mi][ni][3] + b1);
                *reinterpret_cast<float2*>(C + (size_t)r1 * ldc + coloff + c) = o;
            }
        }
    }
}

// ---------------- TF32 GEMM + fused LayerNorm (Wo variant, dynamic smem) ----------
__global__ __launch_bounds__(256) void gemm_tf32_ln(
    const float* __restrict__ A, const float* __restrict__ W,
    const float* __restrict__ bias,
    const float* __restrict__ gamma, const float* __restrict__ beta,
    float* __restrict__ out)
{
    extern __shared__ char sm_[];
    typedef unsigned AsT[BK][136];
    typedef unsigned BsT[BK][128];
    AsT* As = reinterpret_cast<AsT*>(sm_);               // As[2]: 17408 B
    BsT* Bs = reinterpret_cast<BsT*>(sm_ + 17408);       // Bs[2]: 16384 B
    float (*Ct)[132] = reinterpret_cast<float(*)[132]>(sm_);  // epilogue overlay: 67584 B

    const int t    = threadIdx.x;
    const int wid  = t >> 5;
    const int lane = t & 31;
    const int wm   = wid & 1;
    const int wn   = wid >> 1;
    const int tig  = lane & 3;
    const int grp  = lane >> 2;
    const int rowBase = blockIdx.x * 128;

    float acc[4][4][4];
#pragma unroll
    for (int mi = 0; mi < 4; mi++)
#pragma unroll
        for (int ni = 0; ni < 4; ni++)
#pragma unroll
            for (int r = 0; r < 4; r++) acc[mi][ni][r] = 0.f;

    const int aRow0 = t >> 2;
    const int aC0   = (t & 3) << 2;
    const int aRow1 = (t + 256) >> 2;
    const int bK0 = t >> 5;
    const int bN0 = (t & 31) << 2;
    const int bK1 = bK0 + 8;

    const bool aOk0 = rowBase + aRow0 < NN;
    const bool aOk1 = rowBase + aRow1 < NN;
    const float* aP0 = A + (size_t)(rowBase + aRow0) * 128 + aC0;
    const float* aP1 = A + (size_t)(rowBase + aRow1) * 128 + aC0;

    float4 fa0 = make_float4(0.f,0.f,0.f,0.f), fa1 = fa0, fb0, fb1;
    if (aOk0) fa0 = *reinterpret_cast<const float4*>(aP0);
    if (aOk1) fa1 = *reinterpret_cast<const float4*>(aP1);
    fb0 = *reinterpret_cast<const float4*>(W + (size_t)bK0 * 128 + bN0);
    fb1 = *reinterpret_cast<const float4*>(W + (size_t)bK1 * 128 + bN0);

    int buf = 0;
    {
        As[0][aC0+0][aRow0] = f2tf32(fa0.x); As[0][aC0+1][aRow0] = f2tf32(fa0.y);
        As[0][aC0+2][aRow0] = f2tf32(fa0.z); As[0][aC0+3][aRow0] = f2tf32(fa0.w);
        As[0][aC0+0][aRow1] = f2tf32(fa1.x); As[0][aC0+1][aRow1] = f2tf32(fa1.y);
        As[0][aC0+2][aRow1] = f2tf32(fa1.z); As[0][aC0+3][aRow1] = f2tf32(fa1.w);
        Bs[0][bK0][bN0+0] = f2tf32(fb0.x); Bs[0][bK0][bN0+1] = f2tf32(fb0.y);
        Bs[0][bK0][bN0+2] = f2tf32(fb0.z); Bs[0][bK0][bN0+3] = f2tf32(fb0.w);
        Bs[0][bK1][bN0+0] = f2tf32(fb1.x); Bs[0][bK1][bN0+1] = f2tf32(fb1.y);
        Bs[0][bK1][bN0+2] = f2tf32(fb1.z); Bs[0][bK1][bN0+3] = f2tf32(fb1.w);
    }
    __syncthreads();

    for (int kb = 0; kb < 8; kb++) {
        const int nk = (kb + 1) * BK;
        if (kb < 7) {
            fa0 = make_float4(0.f,0.f,0.f,0.f); fa1 = fa0;
            if (aOk0) fa0 = *reinterpret_cast<const float4*>(aP0 + nk);
            if (aOk1) fa1 = *reinterpret_cast<const float4*>(aP1 + nk);
            fb0 = *reinterpret_cast<const float4*>(W + (size_t)(nk + bK0) * 128 + bN0);
            fb1 = *reinterpret_cast<const float4*>(W + (size_t)(nk + bK1) * 128 + bN0);
        }

#pragma unroll
        for (int ks = 0; ks < 2; ks++) {
            const int k0 = ks * 8;
            unsigned a[4][4];
#pragma unroll
            for (int mi = 0; mi < 4; mi++) {
                int mr = wm * 64 + mi * 16 + grp;
                a[mi][0] = As[buf][k0 + tig][mr];
                a[mi][1] = As[buf][k0 + tig][mr + 8];
                a[mi][2] = As[buf][k0 + tig + 4][mr];
                a[mi][3] = As[buf][k0 + tig + 4][mr + 8];
            }
            unsigned b[4][2];
#pragma unroll
            for (int ni = 0; ni < 4; ni++) {
                int nc = wn * 32 + ni * 8 + grp;
                b[ni][0] = Bs[buf][k0 + tig][nc];
                b[ni][1] = Bs[buf][k0 + tig + 4][nc];
            }
#pragma unroll
            for (int mi = 0; mi < 4; mi++)
#pragma unroll
                for (int ni = 0; ni < 4; ni++)
                    mma_tf32(acc[mi][ni][0], acc[mi][ni][1], acc[mi][ni][2], acc[mi][ni][3],
                             a[mi][0], a[mi][1], a[mi][2], a[mi][3],
                             b[ni][0], b[ni][1]);
        }

        if (kb < 7) {
            int nb = buf ^ 1;
            As[nb][aC0+0][aRow0] = f2tf32(fa0.x); As[nb][aC0+1][aRow0] = f2tf32(fa0.y);
            As[nb][aC0+2][aRow0] = f2tf32(fa0.z); As[nb][aC0+3][aRow0] = f2tf32(fa0.w);
            As[nb][aC0+0][aRow1] = f2tf32(fa1.x); As[nb][aC0+1][aRow1] = f2tf32(fa1.y);
            As[nb][aC0+2][aRow1] = f2tf32(fa1.z); As[nb][aC0+3][aRow1] = f2tf32(fa1.w);
            Bs[nb][bK0][bN0+0] = f2tf32(fb0.x); Bs[nb][bK0][bN0+1] = f2tf32(fb0.y);
            Bs[nb][bK0][bN0+2] = f2tf32(fb0.z); Bs[nb][bK0][bN0+3] = f2tf32(fb0.w);
            Bs[nb][bK1][bN0+0] = f2tf32(fb1.x); Bs[nb][bK1][bN0+1] = f2tf32(fb1.y);
            Bs[nb][bK1][bN0+2] = f2tf32(fb1.z); Bs[nb][bK1][bN0+3] = f2tf32(fb1.w);
            __syncthreads();
            buf = nb;
        }
    }

    // ---- epilogue: stage acc+bias into smem tile, then LayerNorm rows ----
    __syncthreads();  // done with As/Bs, reuse as Ct
#pragma unroll
    for (int mi = 0; mi < 4; mi++) {
        int lr0 = wm * 64 + mi * 16 + grp;
        int lr1 = lr0 + 8;
#pragma unroll
        for (int ni = 0; ni < 4; ni++) {
            int c = wn * 32 + ni * 8 + tig * 2;
            float b0 = bias[c], b1 = bias[c + 1];
            Ct[lr0][c]     = acc[mi][ni][0] + b0;
            Ct[lr0][c + 1] = acc[mi][ni][1] + b1;
            Ct[lr1][c]     = acc[mi][ni][2] + b0;
            Ct[lr1][c + 1] = acc[mi][ni][3] + b1;
        }
    }
    __syncthreads();

    // 2 threads per row: thread t -> row t>>1, half (t&1)*64
    {
        int r = t >> 1;
        int half = (t & 1) << 6;
        int grow = rowBase + r;
        if (grow < NN) {
            float s = 0.f;
#pragma unroll
            for (int i = 0; i < 64; i += 4) {
                float4 v = *reinterpret_cast<float4*>(&Ct[r][half + i]);
                s += v.x + v.y + v.z + v.w;
            }
            s += __shfl_xor_sync(0xffffffffu, s, 1);
            float mean = s * (1.0f / 128.0f);

            float s2 = 0.f;
#pragma unroll
            for (int i = 0; i < 64; i += 4) {
                float4 v = *reinterpret_cast<float4*>(&Ct[r][half + i]);
                float dx = v.x - mean, dy = v.y - mean, dz = v.z - mean, dw = v.w - mean;
                s2 += dx * dx + dy * dy + dz * dz + dw * dw;
            }
            s2 += __shfl_xor_sync(0xffffffffu, s2, 1);
            float rstd = rsqrtf(s2 * (1.0f / 128.0f) + 1e-5f);

            float* op = out + (size_t)grow * 128 + half;
#pragma unroll
            for (int i = 0; i < 64; i += 4) {
                float4 v = *reinterpret_cast<float4*>(&Ct[r][half + i]);
                float4 gm = *reinterpret_cast<const float4*>(gamma + half + i);
                float4 bt = *reinterpret_cast<const float4*>(beta + half + i);
                float4 o;
                o.x = (v.x - mean) * rstd * gm.x + bt.x;
                o.y = (v.y - mean) * rstd * gm.y + bt.y;
                o.z = (v.z - mean) * rstd * gm.z + bt.z;
                o.w = (v.w - mean) * rstd * gm.w + bt.w;
                *reinterpret_cast<float4*>(op + i) = o;
            }
        } else {
            // still participate in shuffles deterministically
            float s = 0.f;
            s += __shfl_xor_sync(0xffffffffu, s, 1);
            float s2 = 0.f;
            s2 += __shfl_xor_sync(0xffffffffu, s2, 1);
            (void)s; (void)s2;
        }
    }
}

// ---------------- fused attention: warp per dst node, online softmax, chunk-4 ----------------
__global__ __launch_bounds__(256) void attn_k(
    const int* __restrict__ ei, const float* __restrict__ ea,
    const float* __restrict__ We, const float* __restrict__ be,
    const float* __restrict__ qkv, float* __restrict__ agg)
{
    __shared__ float sWe[256];
    __shared__ float sbe[8];
    {
        int t = threadIdx.x;
        if (t < 256) sWe[t] = We[t];
        if (t < 8) sbe[t] = be[t];
    }
    __syncthreads();

    const int warp = threadIdx.x >> 5;
    const int lane = threadIdx.x & 31;
    const int node = blockIdx.x * 8 + warp;
    if (node >= NN) return;

    const int g = lane >> 2;
    const int j = lane & 3;

    const int beg = g_off[node];
    const int end = g_off[node + 1];

    float* op = &agg[(size_t)node * 128 + lane * 4];
    if (beg == end) {
        *reinterpret_cast<float4*>(op) = make_float4(0.f, 0.f, 0.f, 0.f);
        return;
    }

    float4 qv = *reinterpret_cast<const float4*>(&qkv[(size_t)node * 384 + lane * 4]);
    const float beh = sbe[g];
    const float* wr = &sWe[(j * 8) * 8 + g];

    float m = -__int_as_float(0x7F800000);
    float d = 0.f;
    float4 acc = make_float4(0.f, 0.f, 0.f, 0.f);

    int idx = beg;
    for (; idx + 3 < end; idx += 4) {
        int e0 = g_list[idx], e1 = g_list[idx + 1], e2 = g_list[idx + 2], e3 = g_list[idx + 3];
        int sA = ei[e0], sB = ei[e1], sC = ei[e2], sD = ei[e3];

        float4 k0 = *reinterpret_cast<const float4*>(&qkv[(size_t)sA * 384 + 128 + lane * 4]);
        float4 k1 = *reinterpret_cast<const float4*>(&qkv[(size_t)sB * 384 + 128 + lane * 4]);
        float4 k2 = *reinterpret_cast<const float4*>(&qkv[(size_t)sC * 384 + 128 + lane * 4]);
        float4 k3 = *reinterpret_cast<const float4*>(&qkv[(size_t)sD * 384 + 128 + lane * 4]);

        const float4* p0 = reinterpret_cast<const float4*>(ea + (size_t)e0 * 32 + j * 8);
        const float4* p1 = reinterpret_cast<const float4*>(ea + (size_t)e1 * 32 + j * 8);
        const float4* p2 = reinterpret_cast<const float4*>(ea + (size_t)e2 * 32 + j * 8);
        const float4* p3 = reinterpret_cast<const float4*>(ea + (size_t)e3 * 32 + j * 8);
        float4 a00 = p0[0], a01 = p0[1];
        float4 a10 = p1[0], a11 = p1[1];
        float4 a20 = p2[0], a21 = p2[1];
        float4 a30 = p3[0], a31 = p3[1];

        float4 v0 = *reinterpret_cast<const float4*>(&qkv[(size_t)sA * 384 + 256 + lane * 4]);
        float4 v1 = *reinterpret_cast<const float4*>(&qkv[(size_t)sB * 384 + 256 + lane * 4]);
        float4 v2 = *reinterpret_cast<const float4*>(&qkv[(size_t)sC * 384 + 256 + lane * 4]);
        float4 v3 = *reinterpret_cast<const float4*>(&qkv[(size_t)sD * 384 + 256 + lane * 4]);

        float t0 = (qv.x*k0.x + qv.y*k0.y + qv.z*k0.z + qv.w*k0.w) * 0.25f
                 + a00.x*wr[0] + a00.y*wr[8] + a00.z*wr[16] + a00.w*wr[24]
                 + a01.x*wr[32] + a01.y*wr[40] + a01.z*wr[48] + a01.w*wr[56];
        float t1 = (qv.x*k1.x + qv.y*k1.y + qv.z*k1.z + qv.w*k1.w) * 0.25f
                 + a10.x*wr[0] + a10.y*wr[8] + a10.z*wr[16] + a10.w*wr[24]
                 + a11.x*wr[32] + a11.y*wr[40] + a11.z*wr[48] + a11.w*wr[56];
        float t2 = (qv.x*k2.x + qv.y*k2.y + qv.z*k2.z + qv.w*k2.w) * 0.25f
                 + a20.x*wr[0] + a20.y*wr[8] + a20.z*wr[16] + a20.w*wr[24]
                 + a21.x*wr[32] + a21.y*wr[40] + a21.z*wr[48] + a21.w*wr[56];
        float t3 = (qv.x*k3.x + qv.y*k3.y + qv.z*k3.z + qv.w*k3.w) * 0.25f
                 + a30.x*wr[0] + a30.y*wr[8] + a30.z*wr[16] + a30.w*wr[24]
                 + a31.x*wr[32] + a31.y*wr[40] + a31.z*wr[48] + a31.w*wr[56];

        t0 += __shfl_xor_sync(0xffffffffu, t0, 1);
        t1 += __shfl_xor_sync(0xffffffffu, t1, 1);
        t2 += __shfl_xor_sync(0xffffffffu, t2, 1);
        t3 += __shfl_xor_sync(0xffffffffu, t3, 1);
        t0 += __shfl_xor_sync(0xffffffffu, t0, 2);
        t1 += __shfl_xor_sync(0xffffffffu, t1, 2);
        t2 += __shfl_xor_sync(0xffffffffu, t2, 2);
        t3 += __shfl_xor_sync(0xffffffffu, t3, 2);

        float sc0 = t0 + beh, sc1 = t1 + beh, sc2 = t2 + beh, sc3 = t3 + beh;

        float mx = fmaxf(fmaxf(sc0, sc1), fmaxf(sc2, sc3));
        float mn = fmaxf(m, mx);
        float scale = __expf(m - mn);
        float q0 = __expf(sc0 - mn);
        float q1 = __expf(sc1 - mn);
        float q2 = __expf(sc2 - mn);
        float q3 = __expf(sc3 - mn);
        d = d * scale + q0 + q1 + q2 + q3;
        acc.x = acc.x * scale + q0*v0.x + q1*v1.x + q2*v2.x + q3*v3.x;
        acc.y = acc.y * scale + q0*v0.y + q1*v1.y + q2*v2.y + q3*v3.y;
        acc.z = acc.z * scale + q0*v0.z + q1*v1.z + q2*v2.z + q3*v3.z;
        acc.w = acc.w * scale + q0*v0.w + q1*v1.w + q2*v2.w + q3*v3.w;
        m = mn;
    }

    for (; idx < end; idx++) {
        int e = g_list[idx];
        int src = ei[e];
        float4 kv = *reinterpret_cast<const float4*>(&qkv[(size_t)src * 384 + 128 + lane * 4]);
        float4 vv = *reinterpret_cast<const float4*>(&qkv[(size_t)src * 384 + 256 + lane * 4]);
        const float4* ep = reinterpret_cast<const float4*>(ea + (size_t)e * 32 + j * 8);
        float4 e0 = ep[0], e1 = ep[1];

        float s = (qv.x*kv.x + qv.y*kv.y + qv.z*kv.z + qv.w*kv.w) * 0.25f
                + e0.x*wr[0] + e0.y*wr[8] + e0.z*wr[16] + e0.w*wr[24]
                + e1.x*wr[32] + e1.y*wr[40] + e1.z*wr[48] + e1.w*wr[56];
        s += __shfl_xor_sync(0xffffffffu, s, 1);
        s += __shfl_xor_sync(0xffffffffu, s, 2);
        s += beh;

        float mn = fmaxf(m, s);
        float scale = __expf(m - mn);
        float p = __expf(s - mn);
        d = d * scale + p;
        acc.x = acc.x * scale + p * vv.x;
        acc.y = acc.y * scale + p * vv.y;
        acc.z = acc.z * scale + p * vv.z;
        acc.w = acc.w * scale + p * vv.w;
        m = mn;
    }

    float inv = 1.0f / d;
    *reinterpret_cast<float4*>(op) =
        make_float4(acc.x * inv, acc.y * inv, acc.z * inv, acc.w * inv);
}

// ---------------- launch ----------------
extern "C" void kernel_launch(void* const* d_in, const int* in_sizes, int n_in,
                              void* d_out, int out_size)
{
    const float* x     = (const float*)d_in[0];
    const float* ea    = (const float*)d_in[1];
    const float* Wq    = (const float*)d_in[2];
    const float* bq    = (const float*)d_in[3];
    const float* Wk    = (const float*)d_in[4];
    const float* bk    = (const float*)d_in[5];
    const float* Wv    = (const float*)d_in[6];
    const float* bv    = (const float*)d_in[7];
    const float* We    = (const float*)d_in[8];
    const float* be    = (const float*)d_in[9];
    const float* Wo    = (const float*)d_in[10];
    const float* bo    = (const float*)d_in[11];
    const float* gamma = (const float*)d_in[12];
    const float* beta  = (const float*)d_in[13];
    const int*   ei    = (const int*)d_in[14];
    float* out = (float*)d_out;

    float *qkv, *agg;
    cudaGetSymbolAddress((void**)&qkv, g_qkv);
    cudaGetSymbolAddress((void**)&agg, g_agg);

    static bool attrSet = false;
    if (!attrSet) {
        cudaFuncSetAttribute(gemm_tf32_ln,
                             cudaFuncAttributeMaxDynamicSharedMemorySize, 69632);
        attrSet = true;
    }

    const int nTiles = (NN + 127) / 128;
    const size_t lnSmem = 128 * 132 * 4;  // 67584

    // fork: CSR build on side stream, QKV GEMMs on main stream
    cudaEventRecord(s_evFork, 0);
    cudaStreamWaitEvent(s_side, s_evFork, 0);

    zero_cnt_k<<<(NN + 255) / 256, 256, 0, s_side>>>();
    hist_k<<<(EE + 255) / 256, 256, 0, s_side>>>(ei);
    scan_k<<<1, 1024, 0, s_side>>>();
    scatter_k<<<(EE + 255) / 256, 256, 0, s_side>>>(ei);
    cudaEventRecord(s_evJoin, s_side);

    gemm_tf32<<<nTiles, 256>>>(x, Wq, bq, qkv, 384, 0);
    gemm_tf32<<<nTiles, 256>>>(x, Wk, bk, qkv, 384, 128);
    gemm_tf32<<<nTiles, 256>>>(x, Wv, bv, qkv, 384, 256);

    cudaStreamWaitEvent(0, s_evJoin, 0);

    attn_k<<<(NN + 7) / 8, 256>>>(ei, ea, We, be, qkv, agg);

    gemm_tf32_ln<<<nTiles, 256, lnSmem>>>(agg, Wo, bo, gamma, beta, out);
}

// round 5
// speedup vs baseline: 1.0591x; 1.0591x over previous
#include <cuda_runtime.h>
#include <math.h>

#define NN 50000
#define EE 800000

// ---------------- scratch ----------------
__device__ float g_qkv[NN * 384];     // [node][ q | k | v ]
__device__ float g_agg[NN * 128];
__device__ int   g_cnt[NN];
__device__ int   g_off[NN + 1];
__device__ int2  g_list2[EE];         // {edge id, src node} grouped by dst

// ---------------- streams/events ----------------
static cudaStream_t s_side;
static cudaEvent_t  s_evFork, s_evJoin;
static struct StreamInit {
    StreamInit() {
        cudaStreamCreateWithFlags(&s_side, cudaStreamNonBlocking);
        cudaEventCreateWithFlags(&s_evFork, cudaEventDisableTiming);
        cudaEventCreateWithFlags(&s_evJoin, cudaEventDisableTiming);
    }
} s_streamInit;

// ---------------- CSR build ----------------
__global__ void zero_cnt_k() {
    int i = blockIdx.x * blockDim.x + threadIdx.x;
    if (i < NN) g_cnt[i] = 0;
}

__global__ void hist_k(const int* __restrict__ ei) {
    int e = blockIdx.x * blockDim.x + threadIdx.x;
    if (e < EE) atomicAdd(&g_cnt[ei[EE + e]], 1);
}

__global__ __launch_bounds__(1024) void scan_k() {
    __shared__ int ssum[1024];
    const int T = 1024;
    const int CH = (NN + T - 1) / T;
    int t = threadIdx.x;
    int base = t * CH;

    int loc = 0;
    for (int i = 0; i < CH; i++) {
        int idx = base + i;
        if (idx < NN) loc += g_cnt[idx];
    }
    ssum[t] = loc;
    __syncthreads();
    for (int o = 1; o < T; o <<= 1) {
        int v = (t >= o) ? ssum[t - o] : 0;
        __syncthreads();
        ssum[t] += v;
        __syncthreads();
    }
    int run = (t == 0) ? 0 : ssum[t - 1];
    for (int i = 0; i < CH; i++) {
        int idx = base + i;
        if (idx < NN) {
            int c = g_cnt[idx];
            g_off[idx] = run;
            g_cnt[idx] = 0;
            run += c;
        }
    }
    if (t == T - 1) g_off[NN] = run;
}

__global__ void scatter_k(const int* __restrict__ ei) {
    int e = blockIdx.x * blockDim.x + threadIdx.x;
    if (e < EE) {
        int src = ei[e];
        int dst = ei[EE + e];
        int pos = atomicAdd(&g_cnt[dst], 1);
        g_list2[g_off[dst] + pos] = make_int2(e, src);
    }
}

// ---------------- TF32 helpers ----------------
__device__ __forceinline__ unsigned f2tf32(float f) {
    unsigned u;
    asm("cvt.rna.tf32.f32 %0, %1;" : "=r"(u) : "f"(f));
    return u;
}

__device__ __forceinline__ void mma_tf32(
    float& c0, float& c1, float& c2, float& c3,
    unsigned a0, unsigned a1, unsigned a2, unsigned a3,
    unsigned b0, unsigned b1)
{
    asm volatile(
        "mma.sync.aligned.m16n8k8.row.col.f32.tf32.tf32.f32 "
        "{%0,%1,%2,%3}, {%4,%5,%6,%7}, {%8,%9}, {%0,%1,%2,%3};"
        : "+f"(c0), "+f"(c1), "+f"(c2), "+f"(c3)
        : "r"(a0), "r"(a1), "r"(a2), "r"(a3), "r"(b0), "r"(b1));
}

#define BK 16

// ---------------- TF32 GEMM [N,128]x[128,128]+bias (QKV variant) ----------
__global__ __launch_bounds__(256) void gemm_tf32(
    const float* __restrict__ A, const float* __restrict__ W,
    const float* __restrict__ bias, float* __restrict__ C,
    int ldc, int coloff)
{
    __shared__ unsigned As[2][BK][136];
    __shared__ unsigned Bs[2][BK][128];

    const int t    = threadIdx.x;
    const int wid  = t >> 5;
    const int lane = t & 31;
    const int wm   = wid & 1;
    const int wn   = wid >> 1;
    const int tig  = lane & 3;
    const int grp  = lane >> 2;
    const int rowBase = blockIdx.x * 128;

    float acc[4][4][4];
#pragma unroll
    for (int mi = 0; mi < 4; mi++)
#pragma unroll
        for (int ni = 0; ni < 4; ni++)
#pragma unroll
            for (int r = 0; r < 4; r++) acc[mi][ni][r] = 0.f;

    const int aRow0 = t >> 2;
    const int aC0   = (t & 3) << 2;
    const int aRow1 = (t + 256) >> 2;
    const int bK0 = t >> 5;
    const int bN0 = (t & 31) << 2;
    const int bK1 = bK0 + 8;

    const bool aOk0 = rowBase + aRow0 < NN;
    const bool aOk1 = rowBase + aRow1 < NN;
    const float* aP0 = A + (size_t)(rowBase + aRow0) * 128 + aC0;
    const float* aP1 = A + (size_t)(rowBase + aRow1) * 128 + aC0;

    float4 fa0 = make_float4(0.f,0.f,0.f,0.f), fa1 = fa0, fb0, fb1;
    if (aOk0) fa0 = *reinterpret_cast<const float4*>(aP0);
    if (aOk1) fa1 = *reinterpret_cast<const float4*>(aP1);
    fb0 = *reinterpret_cast<const float4*>(W + (size_t)bK0 * 128 + bN0);
    fb1 = *reinterpret_cast<const float4*>(W + (size_t)bK1 * 128 + bN0);

    int buf = 0;
    {
        As[0][aC0+0][aRow0] = f2tf32(fa0.x); As[0][aC0+1][aRow0] = f2tf32(fa0.y);
        As[0][aC0+2][aRow0] = f2tf32(fa0.z); As[0][aC0+3][aRow0] = f2tf32(fa0.w);
        As[0][aC0+0][aRow1] = f2tf32(fa1.x); As[0][aC0+1][aRow1] = f2tf32(fa1.y);
        As[0][aC0+2][aRow1] = f2tf32(fa1.z); As[0][aC0+3][aRow1] = f2tf32(fa1.w);
        Bs[0][bK0][bN0+0] = f2tf32(fb0.x); Bs[0][bK0][bN0+1] = f2tf32(fb0.y);
        Bs[0][bK0][bN0+2] = f2tf32(fb0.z); Bs[0][bK0][bN0+3] = f2tf32(fb0.w);
        Bs[0][bK1][bN0+0] = f2tf32(fb1.x); Bs[0][bK1][bN0+1] = f2tf32(fb1.y);
        Bs[0][bK1][bN0+2] = f2tf32(fb1.z); Bs[0][bK1][bN0+3] = f2tf32(fb1.w);
    }
    __syncthreads();

    for (int kb = 0; kb < 8; kb++) {
        const int nk = (kb + 1) * BK;
        if (kb < 7) {
            fa0 = make_float4(0.f,0.f,0.f,0.f); fa1 = fa0;
            if (aOk0) fa0 = *reinterpret_cast<const float4*>(aP0 + nk);
            if (aOk1) fa1 = *reinterpret_cast<const float4*>(aP1 + nk);
            fb0 = *reinterpret_cast<const float4*>(W + (size_t)(nk + bK0) * 128 + bN0);
            fb1 = *reinterpret_cast<const float4*>(W + (size_t)(nk + bK1) * 128 + bN0);
        }

#pragma unroll
        for (int ks = 0; ks < 2; ks++) {
            const int k0 = ks * 8;
            unsigned a[4][4];
#pragma unroll
            for (int mi = 0; mi < 4; mi++) {
                int mr = wm * 64 + mi * 16 + grp;
                a[mi][0] = As[buf][k0 + tig][mr];
                a[mi][1] = As[buf][k0 + tig][mr + 8];
                a[mi][2] = As[buf][k0 + tig + 4][mr];
                a[mi][3] = As[buf][k0 + tig + 4][mr + 8];
            }
            unsigned b[4][2];
#pragma unroll
            for (int ni = 0; ni < 4; ni++) {
                int nc = wn * 32 + ni * 8 + grp;
                b[ni][0] = Bs[buf][k0 + tig][nc];
                b[ni][1] = Bs[buf][k0 + tig + 4][nc];
            }
#pragma unroll
            for (int mi = 0; mi < 4; mi++)
#pragma unroll
                for (int ni = 0; ni < 4; ni++)
                    mma_tf32(acc[mi][ni][0], acc[mi][ni][1], acc[mi][ni][2], acc[mi][ni][3],
                             a[mi][0], a[mi][1], a[mi][2], a[mi][3],
                             b[ni][0], b[ni][1]);
        }

        if (kb < 7) {
            int nb = buf ^ 1;
            As[nb][aC0+0][aRow0] = f2tf32(fa0.x); As[nb][aC0+1][aRow0] = f2tf32(fa0.y);
            As[nb][aC0+2][aRow0] = f2tf32(fa0.z); As[nb][aC0+3][aRow0] = f2tf32(fa0.w);
            As[nb][aC0+0][aRow1] = f2tf32(fa1.x); As[nb][aC0+1][aRow1] = f2tf32(fa1.y);
            As[nb][aC0+2][aRow1] = f2tf32(fa1.z); As[nb][aC0+3][aRow1] = f2tf32(fa1.w);
            Bs[nb][bK0][bN0+0] = f2tf32(fb0.x); Bs[nb][bK0][bN0+1] = f2tf32(fb0.y);
            Bs[nb][bK0][bN0+2] = f2tf32(fb0.z); Bs[nb][bK0][bN0+3] = f2tf32(fb0.w);
            Bs[nb][bK1][bN0+0] = f2tf32(fb1.x); Bs[nb][bK1][bN0+1] = f2tf32(fb1.y);
            Bs[nb][bK1][bN0+2] = f2tf32(fb1.z); Bs[nb][bK1][bN0+3] = f2tf32(fb1.w);
            __syncthreads();
            buf = nb;
        }
    }

#pragma unroll
    for (int mi = 0; mi < 4; mi++) {
        int r0 = rowBase + wm * 64 + mi * 16 + grp;
        int r1 = r0 + 8;
#pragma unroll
        for (int ni = 0; ni < 4; ni++) {
            int c = wn * 32 + ni * 8 + tig * 2;
            float b0 = bias[c], b1 = bias[c + 1];
            if (r0 < NN) {
                float2 o = make_float2(acc[mi][ni][0] + b0, acc[mi][ni][1] + b1);
                *reinterpret_cast<float2*>(C + (size_t)r0 * ldc + coloff + c) = o;
            }
            if (r1 < NN) {
                float2 o = make_float2(acc[mi][ni][2] + b0, acc[mi][ni][3] + b1);
                *reinterpret_cast<float2*>(C + (size_t)r1 * ldc + coloff + c) = o;
            }
        }
    }
}

// ---------------- TF32 GEMM + fused LayerNorm (Wo variant) ----------
__global__ __launch_bounds__(256) void gemm_tf32_ln(
    const float* __restrict__ A, const float* __restrict__ W,
    const float* __restrict__ bias,
    const float* __restrict__ gamma, const float* __restrict__ beta,
    float* __restrict__ out)
{
    extern __shared__ char sm_[];
    typedef unsigned AsT[BK][136];
    typedef unsigned BsT[BK][128];
    AsT* As = reinterpret_cast<AsT*>(sm_);
    BsT* Bs = reinterpret_cast<BsT*>(sm_ + 17408);
    float (*Ct)[132] = reinterpret_cast<float(*)[132]>(sm_);

    const int t    = threadIdx.x;
    const int wid  = t >> 5;
    const int lane = t & 31;
    const int wm   = wid & 1;
    const int wn   = wid >> 1;
    const int tig  = lane & 3;
    const int grp  = lane >> 2;
    const int rowBase = blockIdx.x * 128;

    float acc[4][4][4];
#pragma unroll
    for (int mi = 0; mi < 4; mi++)
#pragma unroll
        for (int ni = 0; ni < 4; ni++)
#pragma unroll
            for (int r = 0; r < 4; r++) acc[mi][ni][r] = 0.f;

    const int aRow0 = t >> 2;
    const int aC0   = (t & 3) << 2;
    const int aRow1 = (t + 256) >> 2;
    const int bK0 = t >> 5;
    const int bN0 = (t & 31) << 2;
    const int bK1 = bK0 + 8;

    const bool aOk0 = rowBase + aRow0 < NN;
    const bool aOk1 = rowBase + aRow1 < NN;
    const float* aP0 = A + (size_t)(rowBase + aRow0) * 128 + aC0;
    const float* aP1 = A + (size_t)(rowBase + aRow1) * 128 + aC0;

    float4 fa0 = make_float4(0.f,0.f,0.f,0.f), fa1 = fa0, fb0, fb1;
    if (aOk0) fa0 = *reinterpret_cast<const float4*>(aP0);
    if (aOk1) fa1 = *reinterpret_cast<const float4*>(aP1);
    fb0 = *reinterpret_cast<const float4*>(W + (size_t)bK0 * 128 + bN0);
    fb1 = *reinterpret_cast<const float4*>(W + (size_t)bK1 * 128 + bN0);

    int buf = 0;
    {
        As[0][aC0+0][aRow0] = f2tf32(fa0.x); As[0][aC0+1][aRow0] = f2tf32(fa0.y);
        As[0][aC0+2][aRow0] = f2tf32(fa0.z); As[0][aC0+3][aRow0] = f2tf32(fa0.w);
        As[0][aC0+0][aRow1] = f2tf32(fa1.x); As[0][aC0+1][aRow1] = f2tf32(fa1.y);
        As[0][aC0+2][aRow1] = f2tf32(fa1.z); As[0][aC0+3][aRow1] = f2tf32(fa1.w);
        Bs[0][bK0][bN0+0] = f2tf32(fb0.x); Bs[0][bK0][bN0+1] = f2tf32(fb0.y);
        Bs[0][bK0][bN0+2] = f2tf32(fb0.z); Bs[0][bK0][bN0+3] = f2tf32(fb0.w);
        Bs[0][bK1][bN0+0] = f2tf32(fb1.x); Bs[0][bK1][bN0+1] = f2tf32(fb1.y);
        Bs[0][bK1][bN0+2] = f2tf32(fb1.z); Bs[0][bK1][bN0+3] = f2tf32(fb1.w);
    }
    __syncthreads();

    for (int kb = 0; kb < 8; kb++) {
        const int nk = (kb + 1) * BK;
        if (kb < 7) {
            fa0 = make_float4(0.f,0.f,0.f,0.f); fa1 = fa0;
            if (aOk0) fa0 = *reinterpret_cast<const float4*>(aP0 + nk);
            if (aOk1) fa1 = *reinterpret_cast<const float4*>(aP1 + nk);
            fb0 = *reinterpret_cast<const float4*>(W + (size_t)(nk + bK0) * 128 + bN0);
            fb1 = *reinterpret_cast<const float4*>(W + (size_t)(nk + bK1) * 128 + bN0);
        }

#pragma unroll
        for (int ks = 0; ks < 2; ks++) {
            const int k0 = ks * 8;
            unsigned a[4][4];
#pragma unroll
            for (int mi = 0; mi < 4; mi++) {
                int mr = wm * 64 + mi * 16 + grp;
                a[mi][0] = As[buf][k0 + tig][mr];
                a[mi][1] = As[buf][k0 + tig][mr + 8];
                a[mi][2] = As[buf][k0 + tig + 4][mr];
                a[mi][3] = As[buf][k0 + tig + 4][mr + 8];
            }
            unsigned b[4][2];
#pragma unroll
            for (int ni = 0; ni < 4; ni++) {
                int nc = wn * 32 + ni * 8 + grp;
                b[ni][0] = Bs[buf][k0 + tig][nc];
                b[ni][1] = Bs[buf][k0 + tig + 4][nc];
            }
#pragma unroll
            for (int mi = 0; mi < 4; mi++)
#pragma unroll
                for (int ni = 0; ni < 4; ni++)
                    mma_tf32(acc[mi][ni][0], acc[mi][ni][1], acc[mi][ni][2], acc[mi][ni][3],
                             a[mi][0], a[mi][1], a[mi][2], a[mi][3],
                             b[ni][0], b[ni][1]);
        }

        if (kb < 7) {
            int nb = buf ^ 1;
            As[nb][aC0+0][aRow0] = f2tf32(fa0.x); As[nb][aC0+1][aRow0] = f2tf32(fa0.y);
            As[nb][aC0+2][aRow0] = f2tf32(fa0.z); As[nb][aC0+3][aRow0] = f2tf32(fa0.w);
            As[nb][aC0+0][aRow1] = f2tf32(fa1.x); As[nb][aC0+1][aRow1] = f2tf32(fa1.y);
            As[nb][aC0+2][aRow1] = f2tf32(fa1.z); As[nb][aC0+3][aRow1] = f2tf32(fa1.w);
            Bs[nb][bK0][bN0+0] = f2tf32(fb0.x); Bs[nb][bK0][bN0+1] = f2tf32(fb0.y);
            Bs[nb][bK0][bN0+2] = f2tf32(fb0.z); Bs[nb][bK0][bN0+3] = f2tf32(fb0.w);
            Bs[nb][bK1][bN0+0] = f2tf32(fb1.x); Bs[nb][bK1][bN0+1] = f2tf32(fb1.y);
            Bs[nb][bK1][bN0+2] = f2tf32(fb1.z); Bs[nb][bK1][bN0+3] = f2tf32(fb1.w);
            __syncthreads();
            buf = nb;
        }
    }

    __syncthreads();
#pragma unroll
    for (int mi = 0; mi < 4; mi++) {
        int lr0 = wm * 64 + mi * 16 + grp;
        int lr1 = lr0 + 8;
#pragma unroll
        for (int ni = 0; ni < 4; ni++) {
            int c = wn * 32 + ni * 8 + tig * 2;
            float b0 = bias[c], b1 = bias[c + 1];
            Ct[lr0][c]     = acc[mi][ni][0] + b0;
            Ct[lr0][c + 1] = acc[mi][ni][1] + b1;
            Ct[lr1][c]     = acc[mi][ni][2] + b0;
            Ct[lr1][c + 1] = acc[mi][ni][3] + b1;
        }
    }
    __syncthreads();

    {
        int r = t >> 1;
        int half = (t & 1) << 6;
        int grow = rowBase + r;
        if (grow < NN) {
            float s = 0.f;
#pragma unroll
            for (int i = 0; i < 64; i += 4) {
                float4 v = *reinterpret_cast<float4*>(&Ct[r][half + i]);
                s += v.x + v.y + v.z + v.w;
            }
            s += __shfl_xor_sync(0xffffffffu, s, 1);
            float mean = s * (1.0f / 128.0f);

            float s2 = 0.f;
#pragma unroll
            for (int i = 0; i < 64; i += 4) {
                float4 v = *reinterpret_cast<float4*>(&Ct[r][half + i]);
                float dx = v.x - mean, dy = v.y - mean, dz = v.z - mean, dw = v.w - mean;
                s2 += dx * dx + dy * dy + dz * dz + dw * dw;
            }
            s2 += __shfl_xor_sync(0xffffffffu, s2, 1);
            float rstd = rsqrtf(s2 * (1.0f / 128.0f) + 1e-5f);

            float* op = out + (size_t)grow * 128 + half;
#pragma unroll
            for (int i = 0; i < 64; i += 4) {
                float4 v = *reinterpret_cast<float4*>(&Ct[r][half + i]);
                float4 gm = *reinterpret_cast<const float4*>(gamma + half + i);
                float4 bt = *reinterpret_cast<const float4*>(beta + half + i);
                float4 o;
                o.x = (v.x - mean) * rstd * gm.x + bt.x;
                o.y = (v.y - mean) * rstd * gm.y + bt.y;
                o.z = (v.z - mean) * rstd * gm.z + bt.z;
                o.w = (v.w - mean) * rstd * gm.w + bt.w;
                *reinterpret_cast<float4*>(op + i) = o;
            }
        } else {
            float s = 0.f;
            s += __shfl_xor_sync(0xffffffffu, s, 1);
            float s2 = 0.f;
            s2 += __shfl_xor_sync(0xffffffffu, s2, 1);
            (void)s; (void)s2;
        }
    }
}

// ---------------- fused attention: 2 warps per dst node, online softmax ----------------
// Block: 256 thr = 8 warps = 4 nodes x 2 half-warps. Partials combined via smem.
__global__ __launch_bounds__(256) void attn_k(
    const float* __restrict__ ea,
    const float* __restrict__ We, const float* __restrict__ be,
    const float* __restrict__ qkv, float* __restrict__ agg)
{
    __shared__ float  sWe[256];
    __shared__ float  sbe[8];
    __shared__ float4 sAcc[8][32];
    __shared__ float  sM[8][33];
    __shared__ float  sD[8][33];
    {
        int t = threadIdx.x;
        if (t < 256) sWe[t] = We[t];
        if (t < 8) sbe[t] = be[t];
    }
    __syncthreads();

    const int warp = threadIdx.x >> 5;
    const int lane = threadIdx.x & 31;
    const int slot = warp >> 1;        // 0..3 node slot
    const int half = warp & 1;
    const int node = blockIdx.x * 4 + slot;
    const bool valid = node < NN;

    const int g = lane >> 2;
    const int j = lane & 3;

    int beg = 0, end = 0;
    if (valid) { beg = g_off[node]; end = g_off[node + 1]; }
    const int cnt = end - beg;
    const int h0 = (cnt + 1) >> 1;
    const int b  = half ? (beg + h0) : beg;
    const int e_ = half ? end : (beg + h0);

    float4 qv = make_float4(0.f, 0.f, 0.f, 0.f);
    if (valid && cnt > 0)
        qv = *reinterpret_cast<const float4*>(&qkv[(size_t)node * 384 + lane * 4]);
    const float beh = sbe[g];
    const float* wr = &sWe[(j * 8) * 8 + g];

    float m = -__int_as_float(0x7F800000);
    float d = 0.f;
    float4 acc = make_float4(0.f, 0.f, 0.f, 0.f);

    int idx = b;
    for (; idx + 1 < e_; idx += 2) {
        int2 pA = g_list2[idx];
        int2 pB = g_list2[idx + 1];
        int sA = pA.y, sB = pB.y;

        float4 kA = *reinterpret_cast<const float4*>(&qkv[(size_t)sA * 384 + 128 + lane * 4]);
        float4 kB = *reinterpret_cast<const float4*>(&qkv[(size_t)sB * 384 + 128 + lane * 4]);
        float4 vA = *reinterpret_cast<const float4*>(&qkv[(size_t)sA * 384 + 256 + lane * 4]);
        float4 vB = *reinterpret_cast<const float4*>(&qkv[(size_t)sB * 384 + 256 + lane * 4]);
        const float4* epA = reinterpret_cast<const float4*>(ea + (size_t)pA.x * 32 + j * 8);
        const float4* epB = reinterpret_cast<const float4*>(ea + (size_t)pB.x * 32 + j * 8);
        float4 eA0 = epA[0], eA1 = epA[1];
        float4 eB0 = epB[0], eB1 = epB[1];

        float tA = (qv.x*kA.x + qv.y*kA.y + qv.z*kA.z + qv.w*kA.w) * 0.25f
                 + eA0.x*wr[0] + eA0.y*wr[8] + eA0.z*wr[16] + eA0.w*wr[24]
                 + eA1.x*wr[32] + eA1.y*wr[40] + eA1.z*wr[48] + eA1.w*wr[56];
        float tB = (qv.x*kB.x + qv.y*kB.y + qv.z*kB.z + qv.w*kB.w) * 0.25f
                 + eB0.x*wr[0] + eB0.y*wr[8] + eB0.z*wr[16] + eB0.w*wr[24]
                 + eB1.x*wr[32] + eB1.y*wr[40] + eB1.z*wr[48] + eB1.w*wr[56];

        tA += __shfl_xor_sync(0xffffffffu, tA, 1);
        tB += __shfl_xor_sync(0xffffffffu, tB, 1);
        tA += __shfl_xor_sync(0xffffffffu, tA, 2);
        tB += __shfl_xor_sync(0xffffffffu, tB, 2);
        float scA = tA + beh;
        float scB = tB + beh;

        float mn = fmaxf(m, fmaxf(scA, scB));
        float scale = __expf(m - mn);
        float pAe = __expf(scA - mn);
        float pBe = __expf(scB - mn);
        d = d * scale + pAe + pBe;
        acc.x = acc.x * scale + pAe * vA.x + pBe * vB.x;
        acc.y = acc.y * scale + pAe * vA.y + pBe * vB.y;
        acc.z = acc.z * scale + pAe * vA.z + pBe * vB.z;
        acc.w = acc.w * scale + pAe * vA.w + pBe * vB.w;
        m = mn;
    }
    if (idx < e_) {
        int2 pA = g_list2[idx];
        int src = pA.y;
        float4 kv = *reinterpret_cast<const float4*>(&qkv[(size_t)src * 384 + 128 + lane * 4]);
        float4 vv = *reinterpret_cast<const float4*>(&qkv[(size_t)src * 384 + 256 + lane * 4]);
        const float4* ep = reinterpret_cast<const float4*>(ea + (size_t)pA.x * 32 + j * 8);
        float4 e0 = ep[0], e1 = ep[1];

        float s = (qv.x*kv.x + qv.y*kv.y + qv.z*kv.z + qv.w*kv.w) * 0.25f
                + e0.x*wr[0] + e0.y*wr[8] + e0.z*wr[16] + e0.w*wr[24]
                + e1.x*wr[32] + e1.y*wr[40] + e1.z*wr[48] + e1.w*wr[56];
        s += __shfl_xor_sync(0xffffffffu, s, 1);
        s += __shfl_xor_sync(0xffffffffu, s, 2);
        s += beh;

        float mn = fmaxf(m, s);
        float scale = __expf(m - mn);
        float p = __expf(s - mn);
        d = d * scale + p;
        acc.x = acc.x * scale + p * vv.x;
        acc.y = acc.y * scale + p * vv.y;
        acc.z = acc.z * scale + p * vv.z;
        acc.w = acc.w * scale + p * vv.w;
        m = mn;
    }

    sM[warp][lane] = m;
    sD[warp][lane] = d;
    sAcc[warp][lane] = acc;
    __syncthreads();

    if (half == 0 && valid) {
        float* op = &agg[(size_t)node * 128 + lane * 4];
        if (cnt == 0) {
            *reinterpret_cast<float4*>(op) = make_float4(0.f, 0.f, 0.f, 0.f);
        } else {
            float m1 = sM[warp + 1][lane];
            float d1 = sD[warp + 1][lane];
            float4 a1 = sAcc[warp + 1][lane];

            float mn = fmaxf(m, m1);
            float s0 = __expf(m - mn);
            float s1 = (m1 == -__int_as_float(0x7F800000)) ? 0.f : __expf(m1 - mn);
            float dt = d * s0 + d1 * s1;
            float inv = 1.0f / dt;
            float4 o;
            o.x = (acc.x * s0 + a1.x * s1) * inv;
            o.y = (acc.y * s0 + a1.y * s1) * inv;
            o.z = (acc.z * s0 + a1.z * s1) * inv;
            o.w = (acc.w * s0 + a1.w * s1) * inv;
            *reinterpret_cast<float4*>(op) = o;
        }
    }
}

// ---------------- launch ----------------
extern "C" void kernel_launch(void* const* d_in, const int* in_sizes, int n_in,
                              void* d_out, int out_size)
{
    const float* x     = (const float*)d_in[0];
    const float* ea    = (const float*)d_in[1];
    const float* Wq    = (const float*)d_in[2];
    const float* bq    = (const float*)d_in[3];
    const float* Wk    = (const float*)d_in[4];
    const float* bk    = (const float*)d_in[5];
    const float* Wv    = (const float*)d_in[6];
    const float* bv    = (const float*)d_in[7];
    const float* We    = (const float*)d_in[8];
    const float* be    = (const float*)d_in[9];
    const float* Wo    = (const float*)d_in[10];
    const float* bo    = (const float*)d_in[11];
    const float* gamma = (const float*)d_in[12];
    const float* beta  = (const float*)d_in[13];
    const int*   ei    = (const int*)d_in[14];
    float* out = (float*)d_out;

    float *qkv, *agg;
    cudaGetSymbolAddress((void**)&qkv, g_qkv);
    cudaGetSymbolAddress((void**)&agg, g_agg);

    static bool attrSet = false;
    if (!attrSet) {
        cudaFuncSetAttribute(gemm_tf32_ln,
                             cudaFuncAttributeMaxDynamicSharedMemorySize, 69632);
        attrSet = true;
    }

    const int nTiles = (NN + 127) / 128;
    const size_t lnSmem = 128 * 132 * 4;

    cudaEventRecord(s_evFork, 0);
    cudaStreamWaitEvent(s_side, s_evFork, 0);

    zero_cnt_k<<<(NN + 255) / 256, 256, 0, s_side>>>();
    hist_k<<<(EE + 255) / 256, 256, 0, s_side>>>(ei);
    scan_k<<<1, 1024, 0, s_side>>>();
    scatter_k<<<(EE + 255) / 256, 256, 0, s_side>>>(ei);
    cudaEventRecord(s_evJoin, s_side);

    gemm_tf32<<<nTiles, 256>>>(x, Wq, bq, qkv, 384, 0);
    gemm_tf32<<<nTiles, 256>>>(x, Wk, bk, qkv, 384, 128);
    gemm_tf32<<<nTiles, 256>>>(x, Wv, bv, qkv, 384, 256);

    cudaStreamWaitEvent(0, s_evJoin, 0);

    attn_k<<<(NN + 3) / 4, 256>>>(ea, We, be, qkv, agg);

    gemm_tf32_ln<<<nTiles, 256, lnSmem>>>(agg, Wo, bo, gamma, beta, out);
}

// round 6
// speedup vs baseline: 1.1037x; 1.0421x over previous
#include <cuda_runtime.h>
#include <math.h>

#define NN 50000
#define EE 800000

// ---------------- scratch ----------------
__device__ float g_qkv[NN * 384];     // [node][ q | k | v ]
__device__ float g_agg[NN * 128];
__device__ float g_eb [EE * 8];       // per-(edge,head) bias: ea @ We + be
__device__ int   g_cnt[NN];
__device__ int   g_off[NN + 1];
__device__ int2  g_list2[EE];         // {edge id, src node} grouped by dst

// ---------------- streams/events ----------------
static cudaStream_t s_side, s_side2;
static cudaEvent_t  s_evFork, s_evJoin, s_evJoin2;
static struct StreamInit {
    StreamInit() {
        cudaStreamCreateWithFlags(&s_side,  cudaStreamNonBlocking);
        cudaStreamCreateWithFlags(&s_side2, cudaStreamNonBlocking);
        cudaEventCreateWithFlags(&s_evFork,  cudaEventDisableTiming);
        cudaEventCreateWithFlags(&s_evJoin,  cudaEventDisableTiming);
        cudaEventCreateWithFlags(&s_evJoin2, cudaEventDisableTiming);
    }
} s_streamInit;

// ---------------- CSR build ----------------
__global__ void zero_cnt_k() {
    int i = blockIdx.x * blockDim.x + threadIdx.x;
    if (i < NN) g_cnt[i] = 0;
}

__global__ void hist_k(const int* __restrict__ ei) {
    int e = blockIdx.x * blockDim.x + threadIdx.x;
    if (e < EE) atomicAdd(&g_cnt[ei[EE + e]], 1);
}

__global__ __launch_bounds__(1024) void scan_k() {
    __shared__ int ssum[1024];
    const int T = 1024;
    const int CH = (NN + T - 1) / T;
    int t = threadIdx.x;
    int base = t * CH;

    int loc = 0;
    for (int i = 0; i < CH; i++) {
        int idx = base + i;
        if (idx < NN) loc += g_cnt[idx];
    }
    ssum[t] = loc;
    __syncthreads();
    for (int o = 1; o < T; o <<= 1) {
        int v = (t >= o) ? ssum[t - o] : 0;
        __syncthreads();
        ssum[t] += v;
        __syncthreads();
    }
    int run = (t == 0) ? 0 : ssum[t - 1];
    for (int i = 0; i < CH; i++) {
        int idx = base + i;
        if (idx < NN) {
            int c = g_cnt[idx];
            g_off[idx] = run;
            g_cnt[idx] = 0;
            run += c;
        }
    }
    if (t == T - 1) g_off[NN] = run;
}

__global__ void scatter_k(const int* __restrict__ ei) {
    int e = blockIdx.x * blockDim.x + threadIdx.x;
    if (e < EE) {
        int src = ei[e];
        int dst = ei[EE + e];
        int pos = atomicAdd(&g_cnt[dst], 1);
        g_list2[g_off[dst] + pos] = make_int2(e, src);
    }
}

// ---------------- edge-bias precompute: eb[e][h] = ea[e] @ We[:,h] + be[h] ----------------
__global__ __launch_bounds__(256) void ebias_k(
    const float* __restrict__ ea, const float* __restrict__ We,
    const float* __restrict__ be)
{
    __shared__ float sWe[256];
    __shared__ float sbe[8];
    int t = threadIdx.x;
    sWe[t] = We[t];
    if (t < 8) sbe[t] = be[t];
    __syncthreads();

    int gid = blockIdx.x * 256 + t;
    if (gid >= EE * 8) return;
    int e = gid >> 3, h = gid & 7;

    float s = sbe[h];
    const float4* ep = reinterpret_cast<const float4*>(ea + (size_t)e * 32);
#pragma unroll
    for (int i = 0; i < 8; i++) {
        float4 v = ep[i];
        s += v.x * sWe[(i * 4 + 0) * 8 + h] + v.y * sWe[(i * 4 + 1) * 8 + h]
           + v.z * sWe[(i * 4 + 2) * 8 + h] + v.w * sWe[(i * 4 + 3) * 8 + h];
    }
    g_eb[gid] = s;
}

// ---------------- TF32 helpers ----------------
__device__ __forceinline__ unsigned f2tf32(float f) {
    unsigned u;
    asm("cvt.rna.tf32.f32 %0, %1;" : "=r"(u) : "f"(f));
    return u;
}

__device__ __forceinline__ void mma_tf32(
    float& c0, float& c1, float& c2, float& c3,
    unsigned a0, unsigned a1, unsigned a2, unsigned a3,
    unsigned b0, unsigned b1)
{
    asm volatile(
        "mma.sync.aligned.m16n8k8.row.col.f32.tf32.tf32.f32 "
        "{%0,%1,%2,%3}, {%4,%5,%6,%7}, {%8,%9}, {%0,%1,%2,%3};"
        : "+f"(c0), "+f"(c1), "+f"(c2), "+f"(c3)
        : "r"(a0), "r"(a1), "r"(a2), "r"(a3), "r"(b0), "r"(b1));
}

#define BK 16

// ---------------- TF32 GEMM [N,128]x[128,128]+bias (QKV variant) ----------
__global__ __launch_bounds__(256) void gemm_tf32(
    const float* __restrict__ A, const float* __restrict__ W,
    const float* __restrict__ bias, float* __restrict__ C,
    int ldc, int coloff)
{
    __shared__ unsigned As[2][BK][136];
    __shared__ unsigned Bs[2][BK][128];

    const int t    = threadIdx.x;
    const int wid  = t >> 5;
    const int lane = t & 31;
    const int wm   = wid & 1;
    const int wn   = wid >> 1;
    const int tig  = lane & 3;
    const int grp  = lane >> 2;
    const int rowBase = blockIdx.x * 128;

    float acc[4][4][4];
#pragma unroll
    for (int mi = 0; mi < 4; mi++)
#pragma unroll
        for (int ni = 0; ni < 4; ni++)
#pragma unroll
            for (int r = 0; r < 4; r++) acc[mi][ni][r] = 0.f;

    const int aRow0 = t >> 2;
    const int aC0   = (t & 3) << 2;
    const int aRow1 = (t + 256) >> 2;
    const int bK0 = t >> 5;
    const int bN0 = (t & 31) << 2;
    const int bK1 = bK0 + 8;

    const bool aOk0 = rowBase + aRow0 < NN;
    const bool aOk1 = rowBase + aRow1 < NN;
    const float* aP0 = A + (size_t)(rowBase + aRow0) * 128 + aC0;
    const float* aP1 = A + (size_t)(rowBase + aRow1) * 128 + aC0;

    float4 fa0 = make_float4(0.f,0.f,0.f,0.f), fa1 = fa0, fb0, fb1;
    if (aOk0) fa0 = *reinterpret_cast<const float4*>(aP0);
    if (aOk1) fa1 = *reinterpret_cast<const float4*>(aP1);
    fb0 = *reinterpret_cast<const float4*>(W + (size_t)bK0 * 128 + bN0);
    fb1 = *reinterpret_cast<const float4*>(W + (size_t)bK1 * 128 + bN0);

    int buf = 0;
    {
        As[0][aC0+0][aRow0] = f2tf32(fa0.x); As[0][aC0+1][aRow0] = f2tf32(fa0.y);
        As[0][aC0+2][aRow0] = f2tf32(fa0.z); As[0][aC0+3][aRow0] = f2tf32(fa0.w);
        As[0][aC0+0][aRow1] = f2tf32(fa1.x); As[0][aC0+1][aRow1] = f2tf32(fa1.y);
        As[0][aC0+2][aRow1] = f2tf32(fa1.z); As[0][aC0+3][aRow1] = f2tf32(fa1.w);
        Bs[0][bK0][bN0+0] = f2tf32(fb0.x); Bs[0][bK0][bN0+1] = f2tf32(fb0.y);
        Bs[0][bK0][bN0+2] = f2tf32(fb0.z); Bs[0][bK0][bN0+3] = f2tf32(fb0.w);
        Bs[0][bK1][bN0+0] = f2tf32(fb1.x); Bs[0][bK1][bN0+1] = f2tf32(fb1.y);
        Bs[0][bK1][bN0+2] = f2tf32(fb1.z); Bs[0][bK1][bN0+3] = f2tf32(fb1.w);
    }
    __syncthreads();

    for (int kb = 0; kb < 8; kb++) {
        const int nk = (kb + 1) * BK;
        if (kb < 7) {
            fa0 = make_float4(0.f,0.f,0.f,0.f); fa1 = fa0;
            if (aOk0) fa0 = *reinterpret_cast<const float4*>(aP0 + nk);
            if (aOk1) fa1 = *reinterpret_cast<const float4*>(aP1 + nk);
            fb0 = *reinterpret_cast<const float4*>(W + (size_t)(nk + bK0) * 128 + bN0);
            fb1 = *reinterpret_cast<const float4*>(W + (size_t)(nk + bK1) * 128 + bN0);
        }

#pragma unroll
        for (int ks = 0; ks < 2; ks++) {
            const int k0 = ks * 8;
            unsigned a[4][4];
#pragma unroll
            for (int mi = 0; mi < 4; mi++) {
                int mr = wm * 64 + mi * 16 + grp;
                a[mi][0] = As[buf][k0 + tig][mr];
                a[mi][1] = As[buf][k0 + tig][mr + 8];
                a[mi][2] = As[buf][k0 + tig + 4][mr];
                a[mi][3] = As[buf][k0 + tig + 4][mr + 8];
            }
            unsigned b[4][2];
#pragma unroll
            for (int ni = 0; ni < 4; ni++) {
                int nc = wn * 32 + ni * 8 + grp;
                b[ni][0] = Bs[buf][k0 + tig][nc];
                b[ni][1] = Bs[buf][k0 + tig + 4][nc];
            }
#pragma unroll
            for (int mi = 0; mi < 4; mi++)
#pragma unroll
                for (int ni = 0; ni < 4; ni++)
                    mma_tf32(acc[mi][ni][0], acc[mi][ni][1], acc[mi][ni][2], acc[mi][ni][3],
                             a[mi][0], a[mi][1], a[mi][2], a[mi][3],
                             b[ni][0], b[ni][1]);
        }

        if (kb < 7) {
            int nb = buf ^ 1;
            As[nb][aC0+0][aRow0] = f2tf32(fa0.x); As[nb][aC0+1][aRow0] = f2tf32(fa0.y);
            As[nb][aC0+2][aRow0] = f2tf32(fa0.z); As[nb][aC0+3][aRow0] = f2tf32(fa0.w);
            As[nb][aC0+0][aRow1] = f2tf32(fa1.x); As[nb][aC0+1][aRow1] = f2tf32(fa1.y);
            As[nb][aC0+2][aRow1] = f2tf32(fa1.z); As[nb][aC0+3][aRow1] = f2tf32(fa1.w);
            Bs[nb][bK0][bN0+0] = f2tf32(fb0.x); Bs[nb][bK0][bN0+1] = f2tf32(fb0.y);
            Bs[nb][bK0][bN0+2] = f2tf32(fb0.z); Bs[nb][bK0][bN0+3] = f2tf32(fb0.w);
            Bs[nb][bK1][bN0+0] = f2tf32(fb1.x); Bs[nb][bK1][bN0+1] = f2tf32(fb1.y);
            Bs[nb][bK1][bN0+2] = f2tf32(fb1.z); Bs[nb][bK1][bN0+3] = f2tf32(fb1.w);
            __syncthreads();
            buf = nb;
        }
    }

#pragma unroll
    for (int mi = 0; mi < 4; mi++) {
        int r0 = rowBase + wm * 64 + mi * 16 + grp;
        int r1 = r0 + 8;
#pragma unroll
        for (int ni = 0; ni < 4; ni++) {
            int c = wn * 32 + ni * 8 + tig * 2;
            float b0 = bias[c], b1 = bias[c + 1];
            if (r0 < NN) {
                float2 o = make_float2(acc[mi][ni][0] + b0, acc[mi][ni][1] + b1);
                *reinterpret_cast<float2*>(C + (size_t)r0 * ldc + coloff + c) = o;
            }
            if (r1 < NN) {
                float2 o = make_float2(acc[mi][ni][2] + b0, acc[mi][ni][3] + b1);
                *reinterpret_cast<float2*>(C + (size_t)r1 * ldc + coloff + c) = o;
            }
        }
    }
}

// ---------------- TF32 GEMM + fused LayerNorm (Wo variant) ----------
__global__ __launch_bounds__(256) void gemm_tf32_ln(
    const float* __restrict__ A, const float* __restrict__ W,
    const float* __restrict__ bias,
    const float* __restrict__ gamma, const float* __restrict__ beta,
    float* __restrict__ out)
{
    extern __shared__ char sm_[];
    typedef unsigned AsT[BK][136];
    typedef unsigned BsT[BK][128];
    AsT* As = reinterpret_cast<AsT*>(sm_);
    BsT* Bs = reinterpret_cast<BsT*>(sm_ + 17408);
    float (*Ct)[132] = reinterpret_cast<float(*)[132]>(sm_);

    const int t    = threadIdx.x;
    const int wid  = t >> 5;
    const int lane = t & 31;
    const int wm   = wid & 1;
    const int wn   = wid >> 1;
    const int tig  = lane & 3;
    const int grp  = lane >> 2;
    const int rowBase = blockIdx.x * 128;

    float acc[4][4][4];
#pragma unroll
    for (int mi = 0; mi < 4; mi++)
#pragma unroll
        for (int ni = 0; ni < 4; ni++)
#pragma unroll
            for (int r = 0; r < 4; r++) acc[mi][ni][r] = 0.f;

    const int aRow0 = t >> 2;
    const int aC0   = (t & 3) << 2;
    const int aRow1 = (t + 256) >> 2;
    const int bK0 = t >> 5;
    const int bN0 = (t & 31) << 2;
    const int bK1 = bK0 + 8;

    const bool aOk0 = rowBase + aRow0 < NN;
    const bool aOk1 = rowBase + aRow1 < NN;
    const float* aP0 = A + (size_t)(rowBase + aRow0) * 128 + aC0;
    const float* aP1 = A + (size_t)(rowBase + aRow1) * 128 + aC0;

    float4 fa0 = make_float4(0.f,0.f,0.f,0.f), fa1 = fa0, fb0, fb1;
    if (aOk0) fa0 = *reinterpret_cast<const float4*>(aP0);
    if (aOk1) fa1 = *reinterpret_cast<const float4*>(aP1);
    fb0 = *reinterpret_cast<const float4*>(W + (size_t)bK0 * 128 + bN0);
    fb1 = *reinterpret_cast<const float4*>(W + (size_t)bK1 * 128 + bN0);

    int buf = 0;
    {
        As[0][aC0+0][aRow0] = f2tf32(fa0.x); As[0][aC0+1][aRow0] = f2tf32(fa0.y);
        As[0][aC0+2][aRow0] = f2tf32(fa0.z); As[0][aC0+3][aRow0] = f2tf32(fa0.w);
        As[0][aC0+0][aRow1] = f2tf32(fa1.x); As[0][aC0+1][aRow1] = f2tf32(fa1.y);
        As[0][aC0+2][aRow1] = f2tf32(fa1.z); As[0][aC0+3][aRow1] = f2tf32(fa1.w);
        Bs[0][bK0][bN0+0] = f2tf32(fb0.x); Bs[0][bK0][bN0+1] = f2tf32(fb0.y);
        Bs[0][bK0][bN0+2] = f2tf32(fb0.z); Bs[0][bK0][bN0+3] = f2tf32(fb0.w);
        Bs[0][bK1][bN0+0] = f2tf32(fb1.x); Bs[0][bK1][bN0+1] = f2tf32(fb1.y);
        Bs[0][bK1][bN0+2] = f2tf32(fb1.z); Bs[0][bK1][bN0+3] = f2tf32(fb1.w);
    }
    __syncthreads();

    for (int kb = 0; kb < 8; kb++) {
        const int nk = (kb + 1) * BK;
        if (kb < 7) {
            fa0 = make_float4(0.f,0.f,0.f,0.f); fa1 = fa0;
            if (aOk0) fa0 = *reinterpret_cast<const float4*>(aP0 + nk);
            if (aOk1) fa1 = *reinterpret_cast<const float4*>(aP1 + nk);
            fb0 = *reinterpret_cast<const float4*>(W + (size_t)(nk + bK0) * 128 + bN0);
            fb1 = *reinterpret_cast<const float4*>(W + (size_t)(nk + bK1) * 128 + bN0);
        }

#pragma unroll
        for (int ks = 0; ks < 2; ks++) {
            const int k0 = ks * 8;
            unsigned a[4][4];
#pragma unroll
            for (int mi = 0; mi < 4; mi++) {
                int mr = wm * 64 + mi * 16 + grp;
                a[mi][0] = As[buf][k0 + tig][mr];
                a[mi][1] = As[buf][k0 + tig][mr + 8];
                a[mi][2] = As[buf][k0 + tig + 4][mr];
                a[mi][3] = As[buf][k0 + tig + 4][mr + 8];
            }
            unsigned b[4][2];
#pragma unroll
            for (int ni = 0; ni < 4; ni++) {
                int nc = wn * 32 + ni * 8 + grp;
                b[ni][0] = Bs[buf][k0 + tig][nc];
                b[ni][1] = Bs[buf][k0 + tig + 4][nc];
            }
#pragma unroll
            for (int mi = 0; mi < 4; mi++)
#pragma unroll
                for (int ni = 0; ni < 4; ni++)
                    mma_tf32(acc[mi][ni][0], acc[mi][ni][1], acc[mi][ni][2], acc[mi][ni][3],
                             a[mi][0], a[mi][1], a[mi][2], a[mi][3],
                             b[ni][0], b[ni][1]);
        }

        if (kb < 7) {
            int nb = buf ^ 1;
            As[nb][aC0+0][aRow0] = f2tf32(fa0.x); As[nb][aC0+1][aRow0] = f2tf32(fa0.y);
            As[nb][aC0+2][aRow0] = f2tf32(fa0.z); As[nb][aC0+3][aRow0] = f2tf32(fa0.w);
            As[nb][aC0+0][aRow1] = f2tf32(fa1.x); As[nb][aC0+1][aRow1] = f2tf32(fa1.y);
            As[nb][aC0+2][aRow1] = f2tf32(fa1.z); As[nb][aC0+3][aRow1] = f2tf32(fa1.w);
            Bs[nb][bK0][bN0+0] = f2tf32(fb0.x); Bs[nb][bK0][bN0+1] = f2tf32(fb0.y);
            Bs[nb][bK0][bN0+2] = f2tf32(fb0.z); Bs[nb][bK0][bN0+3] = f2tf32(fb0.w);
            Bs[nb][bK1][bN0+0] = f2tf32(fb1.x); Bs[nb][bK1][bN0+1] = f2tf32(fb1.y);
            Bs[nb][bK1][bN0+2] = f2tf32(fb1.z); Bs[nb][bK1][bN0+3] = f2tf32(fb1.w);
            __syncthreads();
            buf = nb;
        }
    }

    __syncthreads();
#pragma unroll
    for (int mi = 0; mi < 4; mi++) {
        int lr0 = wm * 64 + mi * 16 + grp;
        int lr1 = lr0 + 8;
#pragma unroll
        for (int ni = 0; ni < 4; ni++) {
            int c = wn * 32 + ni * 8 + tig * 2;
            float b0 = bias[c], b1 = bias[c + 1];
            Ct[lr0][c]     = acc[mi][ni][0] + b0;
            Ct[lr0][c + 1] = acc[mi][ni][1] + b1;
            Ct[lr1][c]     = acc[mi][ni][2] + b0;
            Ct[lr1][c + 1] = acc[mi][ni][3] + b1;
        }
    }
    __syncthreads();

    {
        int r = t >> 1;
        int half = (t & 1) << 6;
        int grow = rowBase + r;
        if (grow < NN) {
            float s = 0.f;
#pragma unroll
            for (int i = 0; i < 64; i += 4) {
                float4 v = *reinterpret_cast<float4*>(&Ct[r][half + i]);
                s += v.x + v.y + v.z + v.w;
            }
            s += __shfl_xor_sync(0xffffffffu, s, 1);
            float mean = s * (1.0f / 128.0f);

            float s2 = 0.f;
#pragma unroll
            for (int i = 0; i < 64; i += 4) {
                float4 v = *reinterpret_cast<float4*>(&Ct[r][half + i]);
                float dx = v.x - mean, dy = v.y - mean, dz = v.z - mean, dw = v.w - mean;
                s2 += dx * dx + dy * dy + dz * dz + dw * dw;
            }
            s2 += __shfl_xor_sync(0xffffffffu, s2, 1);
            float rstd = rsqrtf(s2 * (1.0f / 128.0f) + 1e-5f);

            float* op = out + (size_t)grow * 128 + half;
#pragma unroll
            for (int i = 0; i < 64; i += 4) {
                float4 v = *reinterpret_cast<float4*>(&Ct[r][half + i]);
                float4 gm = *reinterpret_cast<const float4*>(gamma + half + i);
                float4 bt = *reinterpret_cast<const float4*>(beta + half + i);
                float4 o;
                o.x = (v.x - mean) * rstd * gm.x + bt.x;
                o.y = (v.y - mean) * rstd * gm.y + bt.y;
                o.z = (v.z - mean) * rstd * gm.z + bt.z;
                o.w = (v.w - mean) * rstd * gm.w + bt.w;
                *reinterpret_cast<float4*>(op + i) = o;
            }
        } else {
            float s = 0.f;
            s += __shfl_xor_sync(0xffffffffu, s, 1);
            float s2 = 0.f;
            s2 += __shfl_xor_sync(0xffffffffu, s2, 1);
            (void)s; (void)s2;
        }
    }
}

// ---------------- fused attention: 2 warps/node, chunk-4, precomputed edge bias ----------------
__global__ __launch_bounds__(256) void attn_k(
    const float* __restrict__ qkv, float* __restrict__ agg)
{
    __shared__ float4 sAcc[8][32];
    __shared__ float  sM[8][33];
    __shared__ float  sD[8][33];

    const int warp = threadIdx.x >> 5;
    const int lane = threadIdx.x & 31;
    const int slot = warp >> 1;
    const int half = warp & 1;
    const int node = blockIdx.x * 4 + slot;
    const bool valid = node < NN;

    const int g = lane >> 2;

    int beg = 0, end = 0;
    if (valid) { beg = g_off[node]; end = g_off[node + 1]; }
    const int cnt = end - beg;
    const int h0 = (cnt + 1) >> 1;
    const int b  = half ? (beg + h0) : beg;
    const int e_ = half ? end : (beg + h0);

    float4 qv = make_float4(0.f, 0.f, 0.f, 0.f);
    if (valid && cnt > 0)
        qv = *reinterpret_cast<const float4*>(&qkv[(size_t)node * 384 + lane * 4]);

    const float NEG_INF = -__int_as_float(0x7F800000);
    float m = NEG_INF;
    float d = 0.f;
    float4 acc = make_float4(0.f, 0.f, 0.f, 0.f);

    int idx = b;
    for (; idx + 3 < e_; idx += 4) {
        int2 p0 = g_list2[idx];
        int2 p1 = g_list2[idx + 1];
        int2 p2 = g_list2[idx + 2];
        int2 p3 = g_list2[idx + 3];

        // issue all gathers up front: 4 k, 4 v, 4 eb
        float4 k0 = *reinterpret_cast<const float4*>(&qkv[(size_t)p0.y * 384 + 128 + lane * 4]);
        float4 k1 = *reinterpret_cast<const float4*>(&qkv[(size_t)p1.y * 384 + 128 + lane * 4]);
        float4 k2 = *reinterpret_cast<const float4*>(&qkv[(size_t)p2.y * 384 + 128 + lane * 4]);
        float4 k3 = *reinterpret_cast<const float4*>(&qkv[(size_t)p3.y * 384 + 128 + lane * 4]);
        float4 v0 = *reinterpret_cast<const float4*>(&qkv[(size_t)p0.y * 384 + 256 + lane * 4]);
        float4 v1 = *reinterpret_cast<const float4*>(&qkv[(size_t)p1.y * 384 + 256 + lane * 4]);
        float4 v2 = *reinterpret_cast<const float4*>(&qkv[(size_t)p2.y * 384 + 256 + lane * 4]);
        float4 v3 = *reinterpret_cast<const float4*>(&qkv[(size_t)p3.y * 384 + 256 + lane * 4]);
        float eb0 = g_eb[(size_t)p0.x * 8 + g];
        float eb1 = g_eb[(size_t)p1.x * 8 + g];
        float eb2 = g_eb[(size_t)p2.x * 8 + g];
        float eb3 = g_eb[(size_t)p3.x * 8 + g];

        float t0 = qv.x*k0.x + qv.y*k0.y + qv.z*k0.z + qv.w*k0.w;
        float t1 = qv.x*k1.x + qv.y*k1.y + qv.z*k1.z + qv.w*k1.w;
        float t2 = qv.x*k2.x + qv.y*k2.y + qv.z*k2.z + qv.w*k2.w;
        float t3 = qv.x*k3.x + qv.y*k3.y + qv.z*k3.z + qv.w*k3.w;

        t0 += __shfl_xor_sync(0xffffffffu, t0, 1);
        t1 += __shfl_xor_sync(0xffffffffu, t1, 1);
        t2 += __shfl_xor_sync(0xffffffffu, t2, 1);
        t3 += __shfl_xor_sync(0xffffffffu, t3, 1);
        t0 += __shfl_xor_sync(0xffffffffu, t0, 2);
        t1 += __shfl_xor_sync(0xffffffffu, t1, 2);
        t2 += __shfl_xor_sync(0xffffffffu, t2, 2);
        t3 += __shfl_xor_sync(0xffffffffu, t3, 2);

        float sc0 = t0 * 0.25f + eb0;
        float sc1 = t1 * 0.25f + eb1;
        float sc2 = t2 * 0.25f + eb2;
        float sc3 = t3 * 0.25f + eb3;

        float mx = fmaxf(fmaxf(sc0, sc1), fmaxf(sc2, sc3));
        float mn = fmaxf(m, mx);
        float scale = __expf(m - mn);
        float q0 = __expf(sc0 - mn);
        float q1 = __expf(sc1 - mn);
        float q2 = __expf(sc2 - mn);
        float q3 = __expf(sc3 - mn);
        d = d * scale + q0 + q1 + q2 + q3;
        acc.x = acc.x * scale + q0*v0.x + q1*v1.x + q2*v2.x + q3*v3.x;
        acc.y = acc.y * scale + q0*v0.y + q1*v1.y + q2*v2.y + q3*v3.y;
        acc.z = acc.z * scale + q0*v0.z + q1*v1.z + q2*v2.z + q3*v3.z;
        acc.w = acc.w * scale + q0*v0.w + q1*v1.w + q2*v2.w + q3*v3.w;
        m = mn;
    }

    for (; idx < e_; idx++) {
        int2 p = g_list2[idx];
        float4 kv = *reinterpret_cast<const float4*>(&qkv[(size_t)p.y * 384 + 128 + lane * 4]);
        float4 vv = *reinterpret_cast<const float4*>(&qkv[(size_t)p.y * 384 + 256 + lane * 4]);
        float eb = g_eb[(size_t)p.x * 8 + g];

        float s = qv.x*kv.x + qv.y*kv.y + qv.z*kv.z + qv.w*kv.w;
        s += __shfl_xor_sync(0xffffffffu, s, 1);
        s += __shfl_xor_sync(0xffffffffu, s, 2);
        s = s * 0.25f + eb;

        float mn = fmaxf(m, s);
        float scale = __expf(m - mn);
        float p_ = __expf(s - mn);
        d = d * scale + p_;
        acc.x = acc.x * scale + p_ * vv.x;
        acc.y = acc.y * scale + p_ * vv.y;
        acc.z = acc.z * scale + p_ * vv.z;
        acc.w = acc.w * scale + p_ * vv.w;
        m = mn;
    }

    sM[warp][lane] = m;
    sD[warp][lane] = d;
    sAcc[warp][lane] = acc;
    __syncthreads();

    if (half == 0 && valid) {
        float* op = &agg[(size_t)node * 128 + lane * 4];
        if (cnt == 0) {
            *reinterpret_cast<float4*>(op) = make_float4(0.f, 0.f, 0.f, 0.f);
        } else {
            float m1 = sM[warp + 1][lane];
            float d1 = sD[warp + 1][lane];
            float4 a1 = sAcc[warp + 1][lane];

            float mn = fmaxf(m, m1);
            float s0 = __expf(m - mn);
            float s1 = (m1 == NEG_INF) ? 0.f : __expf(m1 - mn);
            float dt = d * s0 + d1 * s1;
            float inv = 1.0f / dt;
            float4 o;
            o.x = (acc.x * s0 + a1.x * s1) * inv;
            o.y = (acc.y * s0 + a1.y * s1) * inv;
            o.z = (acc.z * s0 + a1.z * s1) * inv;
            o.w = (acc.w * s0 + a1.w * s1) * inv;
            *reinterpret_cast<float4*>(op) = o;
        }
    }
}

// ---------------- launch ----------------
extern "C" void kernel_launch(void* const* d_in, const int* in_sizes, int n_in,
                              void* d_out, int out_size)
{
    const float* x     = (const float*)d_in[0];
    const float* ea    = (const float*)d_in[1];
    const float* Wq    = (const float*)d_in[2];
    const float* bq    = (const float*)d_in[3];
    const float* Wk    = (const float*)d_in[4];
    const float* bk    = (const float*)d_in[5];
    const float* Wv    = (const float*)d_in[6];
    const float* bv    = (const float*)d_in[7];
    const float* We    = (const float*)d_in[8];
    const float* be    = (const float*)d_in[9];
    const float* Wo    = (const float*)d_in[10];
    const float* bo    = (const float*)d_in[11];
    const float* gamma = (const float*)d_in[12];
    const float* beta  = (const float*)d_in[13];
    const int*   ei    = (const int*)d_in[14];
    float* out = (float*)d_out;

    float *qkv, *agg;
    cudaGetSymbolAddress((void**)&qkv, g_qkv);
    cudaGetSymbolAddress((void**)&agg, g_agg);

    static bool attrSet = false;
    if (!attrSet) {
        cudaFuncSetAttribute(gemm_tf32_ln,
                             cudaFuncAttributeMaxDynamicSharedMemorySize, 69632);
        attrSet = true;
    }

    const int nTiles = (NN + 127) / 128;
    const size_t lnSmem = 128 * 132 * 4;

    cudaEventRecord(s_evFork, 0);
    cudaStreamWaitEvent(s_side,  s_evFork, 0);
    cudaStreamWaitEvent(s_side2, s_evFork, 0);

    // side stream 1: CSR
    zero_cnt_k<<<(NN + 255) / 256, 256, 0, s_side>>>();
    hist_k<<<(EE + 255) / 256, 256, 0, s_side>>>(ei);
    scan_k<<<1, 1024, 0, s_side>>>();
    scatter_k<<<(EE + 255) / 256, 256, 0, s_side>>>(ei);
    cudaEventRecord(s_evJoin, s_side);

    // side stream 2: edge bias
    ebias_k<<<(EE * 8 + 255) / 256, 256, 0, s_side2>>>(ea, We, be);
    cudaEventRecord(s_evJoin2, s_side2);

    // main stream: QKV GEMMs
    gemm_tf32<<<nTiles, 256>>>(x, Wq, bq, qkv, 384, 0);
    gemm_tf32<<<nTiles, 256>>>(x, Wk, bk, qkv, 384, 128);
    gemm_tf32<<<nTiles, 256>>>(x, Wv, bv, qkv, 384, 256);

    cudaStreamWaitEvent(0, s_evJoin, 0);
    cudaStreamWaitEvent(0, s_evJoin2, 0);

    attn_k<<<(NN + 3) / 4, 256>>>(qkv, agg);

    gemm_tf32_ln<<<nTiles, 256, lnSmem>>>(agg, Wo, bo, gamma, beta, out);
}